// round 14
// baseline (speedup 1.0000x reference)
#include <cuda_runtime.h>
#include <cuda_bf16.h>
#include <cuda_fp16.h>

#define B_DIM 512
#define P_DIM 512
#define F_DIM 1024
#define EPS_T 1e-8f

#define SPLITK 16
#define NTILES 64                   // 8x8 tiles of 64x64
#define NUNITS (NTILES * SPLITK)    // 1024
#define GRID_MAIN 444               // 3 CTAs/SM x 148
#define KPITCH 72                   // smem row pitch in u16/half units (144B)

// Scratch (static device globals — no allocation allowed)
__device__ __align__(16) unsigned short g_qx[B_DIM * F_DIM];  // fp16 sigmoid(x) bits
__device__ __align__(16) unsigned short g_qw[P_DIM * F_DIM];  // fp16 sigmoid(w) bits
__device__ __align__(16) float g_S[B_DIM + P_DIM];            // fp32 row sums (of fp16 vals)
__device__ float g_part[SPLITK * B_DIM * P_DIM];              // split-K fp32 partials
__device__ int   g_ctr;                                       // work counter

// ---------------------------------------------------------------------------
__device__ __forceinline__ float sigmoid_fast(float x)
{
    float t;
    asm("tanh.approx.f32 %0, %1;" : "=f"(t) : "f"(x * 0.5f));
    return fmaf(0.5f, t, 0.5f);
}

__device__ __forceinline__ void cp16(void* smem_dst, const void* gsrc)
{
    unsigned sdst = (unsigned)__cvta_generic_to_shared(smem_dst);
    asm volatile("cp.async.cg.shared.global [%0], [%1], 16;"
                 :: "r"(sdst), "l"(gsrc));
}

// ---------------------------------------------------------------------------
// Kernel 1: sigmoid -> fp16 pairs + fp32 row sums of the fp16-rounded values.
// 256 blocks x 256 threads; each block does 4 rows; each thread MLP=4 loads.
// Also resets g_ctr to GRID_MAIN.
// ---------------------------------------------------------------------------
__global__ __launch_bounds__(256) void prep_kernel(
    const float* __restrict__ x, const float* __restrict__ w)
{
    if (blockIdx.x == 0 && threadIdx.x == 0) g_ctr = GRID_MAIN;

    int tid = threadIdx.x;
    int rb = blockIdx.x * 4;              // 0..1020, never straddles x/w (512%4==0)
    bool isX = (rb < B_DIM);
    const float* src = isX ? (x + (size_t)rb * F_DIM)
                           : (w + (size_t)(rb - B_DIM) * F_DIM);
    unsigned short* dst = isX ? (g_qx + (size_t)rb * F_DIM)
                              : (g_qw + (size_t)(rb - B_DIM) * F_DIM);

    // MLP=4: one float4 per row, 4 rows
    float4 v[4];
    #pragma unroll
    for (int r = 0; r < 4; r++)
        v[r] = reinterpret_cast<const float4*>(src + (size_t)r * F_DIM)[tid];

    float rs[4];
    #pragma unroll
    for (int r = 0; r < 4; r++) {
        float s0 = sigmoid_fast(v[r].x);
        float s1 = sigmoid_fast(v[r].y);
        float s2 = sigmoid_fast(v[r].z);
        float s3 = sigmoid_fast(v[r].w);
        __half2 h01 = __floats2half2_rn(s0, s1);
        __half2 h23 = __floats2half2_rn(s2, s3);
        reinterpret_cast<uint2*>(dst + (size_t)r * F_DIM)[tid] =
            make_uint2(*reinterpret_cast<unsigned*>(&h01),
                       *reinterpret_cast<unsigned*>(&h23));
        // row sums of the ROUNDED values (keeps I and S consistent)
        float2 f01 = __half22float2(h01);
        float2 f23 = __half22float2(h23);
        rs[r] = (f01.x + f01.y) + (f23.x + f23.y);
    }

    #pragma unroll
    for (int r = 0; r < 4; r++)
        #pragma unroll
        for (int o = 16; o > 0; o >>= 1)
            rs[r] += __shfl_xor_sync(0xFFFFFFFFu, rs[r], o);

    __shared__ float red[8][4];
    if ((tid & 31) == 0) {
        #pragma unroll
        for (int r = 0; r < 4; r++) red[tid >> 5][r] = rs[r];
    }
    __syncthreads();
    if (tid < 32) {
        float val = red[tid >> 2][tid & 3];   // warp (tid>>2), row (tid&3)
        val += __shfl_xor_sync(0xFFFFFFFFu, val, 4);
        val += __shfl_xor_sync(0xFFFFFFFFu, val, 8);
        val += __shfl_xor_sync(0xFFFFFFFFu, val, 16);
        if (tid < 4) g_S[rb + tid] = val;
    }
}

// ---------------------------------------------------------------------------
// Kernel 2: persistent fp16 min-sum: HMNMX2 (alu) + HADD2 tree (fma) dual-pipe,
// fp32 widen every 16 k-elements. Dynamic queue, cp.async double buffer.
// Unit = 64x64 tile x KC=64 k. 1024 units, grid 444 x 256, 3 CTAs/SM.
// ---------------------------------------------------------------------------
__global__ __launch_bounds__(256, 3) void tversky_main_kernel()
{
    __shared__ __align__(16) unsigned short xs[2][64][KPITCH];
    __shared__ __align__(16) unsigned short ws[2][64][KPITCH];
    __shared__ int s_uu[2];

    int tid = threadIdx.x;
    int tx = tid & 15;            // N: tx + 16j
    int ty = tid >> 4;            // M: ty + 16i
    int r0 = tid >> 3;            // loader row 0..31 (also r0+32)
    int seg = tid & 7;            // 16B segment

    const uint4* xg4 = reinterpret_cast<const uint4*>(g_qx);
    const uint4* wg4 = reinterpret_cast<const uint4*>(g_qw);

    int u = blockIdx.x;           // static first unit; g_ctr starts at GRID_MAIN
    int cur = 0;

    {   // prologue: stage unit u into buf 0 via cp.async
        int tile = u >> 4, split = u & 15;
        int m0 = (tile >> 3) << 6, n0 = (tile & 7) << 6;
        int kb4 = split << 3;
        cp16(&xs[0][r0][seg * 8],      xg4 + (m0 + r0) * 128 + kb4 + seg);
        cp16(&xs[0][r0 + 32][seg * 8], xg4 + (m0 + r0 + 32) * 128 + kb4 + seg);
        cp16(&ws[0][r0][seg * 8],      wg4 + (n0 + r0) * 128 + kb4 + seg);
        cp16(&ws[0][r0 + 32][seg * 8], wg4 + (n0 + r0 + 32) * 128 + kb4 + seg);
        asm volatile("cp.async.commit_group;" ::: "memory");
    }

    while (u < NUNITS) {
        if (tid == 0) s_uu[cur] = atomicAdd(&g_ctr, 1);
        asm volatile("cp.async.wait_group 0;" ::: "memory");
        __syncthreads();          // buf(cur) complete everywhere; s_uu[cur] visible
        int un = s_uu[cur];

        if (un < NUNITS) {        // stage next unit into other buffer (async)
            int tile = un >> 4, split = un & 15;
            int m0 = (tile >> 3) << 6, n0 = (tile & 7) << 6;
            int kb4 = split << 3;
            int nb = cur ^ 1;
            cp16(&xs[nb][r0][seg * 8],      xg4 + (m0 + r0) * 128 + kb4 + seg);
            cp16(&xs[nb][r0 + 32][seg * 8], xg4 + (m0 + r0 + 32) * 128 + kb4 + seg);
            cp16(&ws[nb][r0][seg * 8],      wg4 + (n0 + r0) * 128 + kb4 + seg);
            cp16(&ws[nb][r0 + 32][seg * 8], wg4 + (n0 + r0 + 32) * 128 + kb4 + seg);
            asm volatile("cp.async.commit_group;" ::: "memory");
        }

        float acc[4][4];
        __half2 chunk[4][4];
        #pragma unroll
        for (int i = 0; i < 4; i++)
            #pragma unroll
            for (int j = 0; j < 4; j++) acc[i][j] = 0.f;

        {   // compute: 64 k (fp16) per unit, 8 per uint4-chunk; widen every 2 chunks
            const unsigned short (*xb)[KPITCH] = xs[cur];
            const unsigned short (*wb)[KPITCH] = ws[cur];
            #pragma unroll
            for (int c = 0; c < 8; c++) {
                uint4 xq[4], wq[4];
                #pragma unroll
                for (int i = 0; i < 4; i++)
                    xq[i] = *reinterpret_cast<const uint4*>(&xb[ty + 16 * i][c * 8]);
                #pragma unroll
                for (int j = 0; j < 4; j++)
                    wq[j] = *reinterpret_cast<const uint4*>(&wb[tx + 16 * j][c * 8]);
                #pragma unroll
                for (int i = 0; i < 4; i++)
                    #pragma unroll
                    for (int j = 0; j < 4; j++) {
                        const __half2* xh = reinterpret_cast<const __half2*>(&xq[i]);
                        const __half2* wh = reinterpret_cast<const __half2*>(&wq[j]);
                        __half2 m0 = __hmin2(xh[0], wh[0]);
                        __half2 m1 = __hmin2(xh[1], wh[1]);
                        __half2 m2 = __hmin2(xh[2], wh[2]);
                        __half2 m3 = __hmin2(xh[3], wh[3]);
                        __half2 t = __hadd2(__hadd2(m0, m1), __hadd2(m2, m3)); // lane<=4
                        if ((c & 1) == 0) {
                            chunk[i][j] = t;
                        } else {
                            __half2 s = __hadd2(chunk[i][j], t);  // lane sum <= 8
                            float2 f = __half22float2(s);
                            acc[i][j] += (f.x + f.y);
                        }
                    }
            }
        }

        // write split-K fp32 partials for unit u
        {
            int tile = u >> 4, split = u & 15;
            int m0 = (tile >> 3) << 6, n0 = (tile & 7) << 6;
            float* pbase = g_part + ((size_t)split * B_DIM + m0) * P_DIM + n0;
            #pragma unroll
            for (int i = 0; i < 4; i++)
                #pragma unroll
                for (int j = 0; j < 4; j++)
                    pbase[(size_t)(ty + 16 * i) * P_DIM + tx + 16 * j] = acc[i][j];
        }

        u = un;
        cur ^= 1;
    }
}

// ---------------------------------------------------------------------------
// Kernel 3: combine 16 split-K partials + Tversky epilogue.
//   out = I / (I + alpha*(Sx-I) + beta*(Sw-I) + eps) + bias
// ---------------------------------------------------------------------------
__global__ __launch_bounds__(256) void finalize_kernel(
    const float* __restrict__ bias,
    const float* __restrict__ alpha,
    const float* __restrict__ beta,
    float* __restrict__ out)
{
    int t4 = blockIdx.x * 256 + threadIdx.x;   // float4 id, 0..65535
    int m  = t4 >> 7;
    int n4 = t4 & 127;

    const float4* pp = reinterpret_cast<const float4*>(g_part) + t4;
    float4 I = make_float4(0.f, 0.f, 0.f, 0.f);
    #pragma unroll
    for (int s = 0; s < SPLITK; s++) {
        float4 v = pp[(size_t)s * (B_DIM * P_DIM / 4)];
        I.x += v.x; I.y += v.y; I.z += v.z; I.w += v.w;
    }

    float Sx = g_S[m];
    float4 Sw = reinterpret_cast<const float4*>(g_S + B_DIM)[n4];

    float a = *alpha;
    float b = *beta;
    float4 bs = reinterpret_cast<const float4*>(bias)[n4];

    float4 o;
    o.x = I.x / (I.x + a * (Sx - I.x) + b * (Sw.x - I.x) + EPS_T) + bs.x;
    o.y = I.y / (I.y + a * (Sx - I.y) + b * (Sw.y - I.y) + EPS_T) + bs.y;
    o.z = I.z / (I.z + a * (Sx - I.z) + b * (Sw.z - I.z) + EPS_T) + bs.z;
    o.w = I.w / (I.w + a * (Sx - I.w) + b * (Sw.w - I.w) + EPS_T) + bs.w;

    reinterpret_cast<float4*>(out)[t4] = o;
}

// ---------------------------------------------------------------------------
extern "C" void kernel_launch(void* const* d_in, const int* in_sizes, int n_in,
                              void* d_out, int out_size)
{
    const float* x      = (const float*)d_in[0];   // (512, 1024)
    const float* weight = (const float*)d_in[1];   // (512, 1024)
    const float* bias   = (const float*)d_in[2];   // (512,)
    const float* alpha  = (const float*)d_in[3];   // scalar
    const float* beta   = (const float*)d_in[4];   // scalar
    float* out = (float*)d_out;                    // (512, 512)

    prep_kernel<<<256, 256>>>(x, weight);
    tversky_main_kernel<<<GRID_MAIN, 256>>>();
    finalize_kernel<<<(B_DIM * P_DIM / 4) / 256, 256>>>(bias, alpha, beta, out);
}